// round 14
// baseline (speedup 1.0000x reference)
#include <cuda_runtime.h>
#include <cuda_fp16.h>
#include <cstdint>
#include <math.h>

// ---------------------------------------------------------------------------
// Problem constants
// ---------------------------------------------------------------------------
#define D        256
#define NROWS    8192
#define LOG_NORM 2.0767937f     // -0.5*ln(2*pi) - ln(0.05)
#define HALF_INV_SIG2 200.0f

// f16 screen: accum err ~1-2e-3 rms; fp32 exp underflows below cos~0.2745.
// Threshold 0.24 -> ~0.035 margin (~20 sigma).
#define SCREEN_T 0.24f

#define TILE_N   128             // Ex rows per CTA (MMA M dim)
#define TILE_M   256             // Ey rows per CTA (MMA N dim)
#define BKB      128             // bytes of K per chunk (64 f16)
#define NCHUNK   4               // K=256 f16 = 512 B/row = 4 chunks
#define NT       512             // 16 warps, warp tile 64(n) x 32(m)

// Scratch (device globals per harness rules)
__device__ float    g_xn[(size_t)NROWS * D];      // normalized fp32
__device__ float    g_yn[(size_t)NROWS * D];
__device__ unsigned g_xh[(size_t)NROWS * (D/2)];  // normalized f16 (packed 2/u32)
__device__ unsigned g_yh[(size_t)NROWS * (D/2)];

// ---------------------------------------------------------------------------
// Helpers
// ---------------------------------------------------------------------------
__device__ __forceinline__ uint32_t smem_u32(const void* p) {
    uint32_t a;
    asm("{ .reg .u64 t; cvta.to.shared.u64 t, %1; cvt.u32.u64 %0, t; }" : "=r"(a) : "l"(p));
    return a;
}
#define SWZ(x) ((x) ^ (((x) >> 3) & 0x70))

__device__ __forceinline__ void cp16(uint32_t s, const void* g) {
    uint64_t ga;
    asm("cvta.to.global.u64 %0, %1;" : "=l"(ga) : "l"(g));
    asm volatile("cp.async.cg.shared.global [%0], [%1], 16;" :: "r"(s), "l"(ga) : "memory");
}
#define CP_COMMIT() asm volatile("cp.async.commit_group;" ::: "memory")
#define CP_WAIT(n)  asm volatile("cp.async.wait_group %0;" :: "n"(n) : "memory")

#define LDSM4(r, addr) \
    asm volatile("ldmatrix.sync.aligned.m8n8.x4.shared.b16 {%0,%1,%2,%3}, [%4];" \
        : "=r"((r)[0]), "=r"((r)[1]), "=r"((r)[2]), "=r"((r)[3]) : "r"(addr))

// f16-accumulate HMMA: m16n8k16, D/C = 2 x .f16x2 regs
#define MMAF16(ac, a, b0, b1) \
    asm volatile("mma.sync.aligned.m16n8k16.row.col.f16.f16.f16.f16 " \
        "{%0,%1},{%2,%3,%4,%5},{%6,%7},{%0,%1};" \
        : "+r"((ac)[0]), "+r"((ac)[1]) \
        : "r"((a)[0]), "r"((a)[1]), "r"((a)[2]), "r"((a)[3]), "r"(b0), "r"(b1))

// SMEM: 2 stages, each A[128][128B] + B[256][128B]
#define A_BYTES     (TILE_N * 128)            // 16384
#define B_BYTES     (TILE_M * 128)            // 32768
#define STAGE_BYTES (A_BYTES + B_BYTES)       // 49152
#define SM_A(s)     ((s) * STAGE_BYTES)
#define SM_B(s)     (SM_A(s) + A_BYTES)
#define SMEM_TOTAL  (2 * STAGE_BYTES)         // 98304

__device__ __forceinline__ unsigned pack2_f16(float a, float b) {
    unsigned short ua = __half_as_ushort(__float2half_rn(a));
    unsigned short ub = __half_as_ushort(__float2half_rn(b));
    return (unsigned)ua | ((unsigned)ub << 16);
}

// ---------------------------------------------------------------------------
// Normalize rows -> fp32 + packed f16 copies. One warp per row.
// Also zeroes out[] (blocks 0-31) — replaces the memset launch.
// ---------------------------------------------------------------------------
__global__ void __launch_bounds__(256) normsplit_kernel(
    const float* __restrict__ Ex, const float* __restrict__ Ey, int N, int M,
    float* __restrict__ out)
{
    if (blockIdx.x < 32) {
        int oi = blockIdx.x * 256 + threadIdx.x;
        if (oi < M) out[oi] = 0.0f;
    }

    int warp = threadIdx.x >> 5, lane = threadIdx.x & 31;
    int row = blockIdx.x * 8 + warp;
    if (row >= N + M) return;

    const float* src; float* dstf; unsigned* dsth; int r;
    if (row < N) { src = Ex; dstf = g_xn; dsth = g_xh; r = row; }
    else         { src = Ey; dstf = g_yn; dsth = g_yh; r = row - N; }

    const float4* s4 = reinterpret_cast<const float4*>(src + (size_t)r * D);
    float4 v0 = s4[lane];
    float4 v1 = s4[lane + 32];

    float ss = v0.x*v0.x + v0.y*v0.y + v0.z*v0.z + v0.w*v0.w
             + v1.x*v1.x + v1.y*v1.y + v1.z*v1.z + v1.w*v1.w;
    #pragma unroll
    for (int off = 16; off > 0; off >>= 1)
        ss += __shfl_xor_sync(0xFFFFFFFFu, ss, off);
    float inv = 1.0f / fmaxf(sqrtf(ss), 1e-8f);

    v0.x *= inv; v0.y *= inv; v0.z *= inv; v0.w *= inv;
    v1.x *= inv; v1.y *= inv; v1.z *= inv; v1.w *= inv;

    float4* d4 = reinterpret_cast<float4*>(dstf + (size_t)r * D);
    d4[lane]      = v0;
    d4[lane + 32] = v1;

    unsigned* dh = dsth + (size_t)r * (D/2);
    dh[2*lane]      = pack2_f16(v0.x, v0.y);
    dh[2*lane + 1]  = pack2_f16(v0.z, v0.w);
    dh[2*lane + 64] = pack2_f16(v1.x, v1.y);
    dh[2*lane + 65] = pack2_f16(v1.z, v1.w);
}

// ---------------------------------------------------------------------------
// Inline exact path: fp32 dot + gaussian + atomicAdd. Called only for the
// ~4k/67M pairs that pass the f16 screen — cost is negligible in aggregate.
// ---------------------------------------------------------------------------
__device__ __noinline__ void exact_add(int n, int m, float* __restrict__ out)
{
    const float4* x = reinterpret_cast<const float4*>(g_xn + (size_t)n * D);
    const float4* y = reinterpret_cast<const float4*>(g_yn + (size_t)m * D);
    float s = 0.0f;
    #pragma unroll
    for (int i = 0; i < 64; i++) {
        float4 a = x[i], b = y[i];
        s = fmaf(a.x, b.x, s); s = fmaf(a.y, b.y, s);
        s = fmaf(a.z, b.z, s); s = fmaf(a.w, b.w, s);
    }
    float dd = s - 1.0f;
    float e = expf(LOG_NORM - HALF_INV_SIG2 * dd * dd);
    if (e != 0.0f) atomicAdd(&out[m], e);
}

// ---------------------------------------------------------------------------
// Screen + fused exact epilogue: f16 HMMA GEMM (f16 accumulate); any pair
// with cos_f16 > 0.24 is recomputed exactly in fp32 and added to out.
// CTA 128(n) x 256(m); 16 warps, warp tile 64(n) x 32(m); 2-stage cp.async.
// ---------------------------------------------------------------------------
__global__ void __launch_bounds__(NT, 1) screen_kernel(float* __restrict__ out)
{
    extern __shared__ __align__(1024) char smem[];
    const uint32_t sb = smem_u32(smem);
    const int t = threadIdx.x;
    const int wid = t >> 5, lane = t & 31;
    const int nBase = blockIdx.y * TILE_N;
    const int mBase = blockIdx.x * TILE_M;
    const int nOff = (wid >> 3) * 64;     // 2 warp-rows
    const int mOff = (wid & 7) * 32;      // 8 warp-cols

    const char* Xp = (const char*)g_xh + (size_t)nBase * 512;   // 512 B/row
    const char* Yp = (const char*)g_yh + (size_t)mBase * 512;

    // acc[mi][n8 block][2 regs], each reg = f16x2 (2 m-cols)
    uint32_t acc[4][4][2];
    #pragma unroll
    for (int mi = 0; mi < 4; mi++)
        #pragma unroll
        for (int j = 0; j < 4; j++) { acc[mi][j][0] = 0u; acc[mi][j][1] = 0u; }

    // Loader for chunk c into stage s: A 1024x16B, B 2048x16B over 512 threads
    #define LOAD_CHUNK(c, s) do {                                              \
        int bkb = (c) * BKB;                                                   \
        _Pragma("unroll")                                                      \
        for (int i = 0; i < 2; i++) {                                          \
            int idx = t + 512 * i; int r = idx >> 3; int kb = (idx & 7) * 16;  \
            cp16(sb + SM_A(s) + SWZ(r * 128 + kb),                             \
                 Xp + (size_t)r * 512 + bkb + kb);                             \
        }                                                                      \
        _Pragma("unroll")                                                      \
        for (int i = 0; i < 4; i++) {                                          \
            int idx = t + 512 * i; int r = idx >> 3; int kb = (idx & 7) * 16;  \
            cp16(sb + SM_B(s) + SWZ(r * 128 + kb),                             \
                 Yp + (size_t)r * 512 + bkb + kb);                             \
        }                                                                      \
        CP_COMMIT();                                                           \
    } while (0)

    LOAD_CHUNK(0, 0);
    LOAD_CHUNK(1, 1);

    // ldmatrix lane addressing (HW-verified layout from R4/R5/R7)
    const int lrow = (lane & 7) + ((lane >> 3) & 1) * 8;
    const int lkb  = (lane >> 4) * 16;

    for (int c = 0; c < NCHUNK; c++) {
        if (c < NCHUNK - 1) CP_WAIT(1); else CP_WAIT(0);
        __syncthreads();
        const int s = c & 1;

        #pragma unroll
        for (int kk = 0; kk < 4; kk++) {          // 4 x k16 per 128B chunk
            uint32_t af[4][4], bf[2][4];
            #pragma unroll
            for (int mi = 0; mi < 4; mi++) {
                uint32_t addr = sb + SM_A(s)
                    + SWZ((nOff + mi * 16 + lrow) * 128 + kk * 32 + lkb);
                LDSM4(af[mi], addr);
            }
            #pragma unroll
            for (int nj = 0; nj < 2; nj++) {
                uint32_t addr = sb + SM_B(s)
                    + SWZ((mOff + nj * 16 + lrow) * 128 + kk * 32 + lkb);
                LDSM4(bf[nj], addr);
            }
            #pragma unroll
            for (int mi = 0; mi < 4; mi++)
                #pragma unroll
                for (int nj = 0; nj < 2; nj++) {
                    MMAF16(acc[mi][2*nj],     af[mi], bf[nj][0], bf[nj][2]);
                    MMAF16(acc[mi][2*nj + 1], af[mi], bf[nj][1], bf[nj][3]);
                }
        }
        __syncthreads();
        if (c + 2 < NCHUNK) LOAD_CHUNK(c + 2, s);
    }

    // Fused epilogue: rare candidates -> exact fp32 recompute + atomicAdd.
    // reg r: rows lane>>2 (+8 for r=1); cols 2(lane&3)+{0,1}
    const int rBase = nBase + nOff + (lane >> 2);
    const int cBase = mBase + mOff + 2 * (lane & 3);
    #pragma unroll
    for (int mi = 0; mi < 4; mi++)
        #pragma unroll
        for (int j = 0; j < 4; j++)
            #pragma unroll
            for (int r = 0; r < 2; r++) {
                __half2 h = *reinterpret_cast<__half2*>(&acc[mi][j][r]);
                float c0 = __low2float(h), c1 = __high2float(h);
                if (c0 > SCREEN_T)
                    exact_add(rBase + mi*16 + r*8, cBase + j*8,     out);
                if (c1 > SCREEN_T)
                    exact_add(rBase + mi*16 + r*8, cBase + j*8 + 1, out);
            }
    #undef LOAD_CHUNK
}

// ---------------------------------------------------------------------------
extern "C" void kernel_launch(void* const* d_in, const int* in_sizes, int n_in,
                              void* d_out, int out_size)
{
    const float* Ex = (const float*)d_in[0];
    const float* Ey = (const float*)d_in[1];
    float* out = (float*)d_out;

    int N = in_sizes[0] / D;   // 8192
    int M = in_sizes[1] / D;   // 8192

    cudaFuncSetAttribute(screen_kernel,
                         cudaFuncAttributeMaxDynamicSharedMemorySize, SMEM_TOTAL);

    normsplit_kernel<<<(N + M + 7) / 8, 256>>>(Ex, Ey, N, M, out);

    dim3 grid(M / TILE_M, N / TILE_N);
    screen_kernel<<<grid, NT, SMEM_TOTAL>>>(out);
}

// round 17
// speedup vs baseline: 1.4736x; 1.4736x over previous
#include <cuda_runtime.h>
#include <cuda_fp16.h>
#include <cstdint>
#include <math.h>

// ---------------------------------------------------------------------------
// Problem constants
// ---------------------------------------------------------------------------
#define D        256
#define NROWS    8192
#define LOG_NORM 2.0767937f     // -0.5*ln(2*pi) - ln(0.05)
#define HALF_INV_SIG2 200.0f

// f16 screen: accum err ~1-2e-3 rms; fp32 exp underflows below cos~0.2745.
// Threshold 0.24 -> ~0.035 margin (~20 sigma).
#define SCREEN_T 0.24f

#define TILE_N   128             // Ex rows per CTA (MMA M dim)
#define TILE_M   128             // Ey rows per CTA (MMA N dim)
#define BKB      128             // bytes of K per chunk (64 f16)
#define NCHUNK   4               // K=256 f16 = 512 B/row = 4 chunks
#define NT       256             // 8 warps, warp tile 64(n) x 32(m)

#define CAP      (1 << 20)

// Scratch (device globals per harness rules)
__device__ float    g_xn[(size_t)NROWS * D];      // normalized fp32
__device__ float    g_yn[(size_t)NROWS * D];
__device__ unsigned g_xh[(size_t)NROWS * (D/2)];  // normalized f16 (packed 2/u32)
__device__ unsigned g_yh[(size_t)NROWS * (D/2)];
__device__ int      g_cnt;
__device__ int2     g_pairs[CAP];

// ---------------------------------------------------------------------------
// Helpers
// ---------------------------------------------------------------------------
__device__ __forceinline__ uint32_t smem_u32(const void* p) {
    uint32_t a;
    asm("{ .reg .u64 t; cvta.to.shared.u64 t, %1; cvt.u32.u64 %0, t; }" : "=r"(a) : "l"(p));
    return a;
}
#define SWZ(x) ((x) ^ (((x) >> 3) & 0x70))

__device__ __forceinline__ void cp16(uint32_t s, const void* g) {
    uint64_t ga;
    asm("cvta.to.global.u64 %0, %1;" : "=l"(ga) : "l"(g));
    asm volatile("cp.async.cg.shared.global [%0], [%1], 16;" :: "r"(s), "l"(ga) : "memory");
}
#define CP_COMMIT() asm volatile("cp.async.commit_group;" ::: "memory")
#define CP_WAIT(n)  asm volatile("cp.async.wait_group %0;" :: "n"(n) : "memory")

#define LDSM4(r, addr) \
    asm volatile("ldmatrix.sync.aligned.m8n8.x4.shared.b16 {%0,%1,%2,%3}, [%4];" \
        : "=r"((r)[0]), "=r"((r)[1]), "=r"((r)[2]), "=r"((r)[3]) : "r"(addr))

// f16-accumulate HMMA: m16n8k16, D/C = 2 x .f16x2 regs
#define MMAF16(ac, a, b0, b1) \
    asm volatile("mma.sync.aligned.m16n8k16.row.col.f16.f16.f16.f16 " \
        "{%0,%1},{%2,%3,%4,%5},{%6,%7},{%0,%1};" \
        : "+r"((ac)[0]), "+r"((ac)[1]) \
        : "r"((a)[0]), "r"((a)[1]), "r"((a)[2]), "r"((a)[3]), "r"(b0), "r"(b1))

// SMEM: 2 stages, each A[128][128B] + B[128][128B] -> 64 KB total
#define A_BYTES     (TILE_N * 128)            // 16384
#define B_BYTES     (TILE_M * 128)            // 16384
#define STAGE_BYTES (A_BYTES + B_BYTES)       // 32768
#define SM_A(s)     ((s) * STAGE_BYTES)
#define SM_B(s)     (SM_A(s) + A_BYTES)
#define SMEM_TOTAL  (2 * STAGE_BYTES)         // 65536 -> 2 CTAs/SM

__device__ __forceinline__ unsigned pack2_f16(float a, float b) {
    unsigned short ua = __half_as_ushort(__float2half_rn(a));
    unsigned short ub = __half_as_ushort(__float2half_rn(b));
    return (unsigned)ua | ((unsigned)ub << 16);
}

// ---------------------------------------------------------------------------
// Normalize rows -> fp32 + packed f16 copies. One warp per row.
// Also resets g_cnt and zeroes out[] (blocks 0-31) — replaces the memset.
// ---------------------------------------------------------------------------
__global__ void __launch_bounds__(256) normsplit_kernel(
    const float* __restrict__ Ex, const float* __restrict__ Ey, int N, int M,
    float* __restrict__ out)
{
    if (blockIdx.x == 0 && threadIdx.x == 0) g_cnt = 0;
    if (blockIdx.x < 32) {
        int oi = blockIdx.x * 256 + threadIdx.x;
        if (oi < M) out[oi] = 0.0f;
    }

    int warp = threadIdx.x >> 5, lane = threadIdx.x & 31;
    int row = blockIdx.x * 8 + warp;
    if (row >= N + M) return;

    const float* src; float* dstf; unsigned* dsth; int r;
    if (row < N) { src = Ex; dstf = g_xn; dsth = g_xh; r = row; }
    else         { src = Ey; dstf = g_yn; dsth = g_yh; r = row - N; }

    const float4* s4 = reinterpret_cast<const float4*>(src + (size_t)r * D);
    float4 v0 = s4[lane];
    float4 v1 = s4[lane + 32];

    float ss = v0.x*v0.x + v0.y*v0.y + v0.z*v0.z + v0.w*v0.w
             + v1.x*v1.x + v1.y*v1.y + v1.z*v1.z + v1.w*v1.w;
    #pragma unroll
    for (int off = 16; off > 0; off >>= 1)
        ss += __shfl_xor_sync(0xFFFFFFFFu, ss, off);
    float inv = 1.0f / fmaxf(sqrtf(ss), 1e-8f);

    v0.x *= inv; v0.y *= inv; v0.z *= inv; v0.w *= inv;
    v1.x *= inv; v1.y *= inv; v1.z *= inv; v1.w *= inv;

    float4* d4 = reinterpret_cast<float4*>(dstf + (size_t)r * D);
    d4[lane]      = v0;
    d4[lane + 32] = v1;

    unsigned* dh = dsth + (size_t)r * (D/2);
    dh[2*lane]      = pack2_f16(v0.x, v0.y);
    dh[2*lane + 1]  = pack2_f16(v0.z, v0.w);
    dh[2*lane + 64] = pack2_f16(v1.x, v1.y);
    dh[2*lane + 65] = pack2_f16(v1.z, v1.w);
}

// ---------------------------------------------------------------------------
// Screen: f16 HMMA GEMM (f16 accumulate), emit pairs cos_f16 > 0.24.
// CTA 128(n) x 128(m); 8 warps (2x4), warp tile 64(n) x 32(m).
// 64 KB smem + <=128 regs (launch_bounds min 2 blocks) -> 2 CTAs/SM:
// two independent barrier domains keep the tensor pipe fed through syncs.
// ---------------------------------------------------------------------------
__global__ void __launch_bounds__(NT, 2) screen_kernel()
{
    extern __shared__ __align__(1024) char smem[];
    const uint32_t sb = smem_u32(smem);
    const int t = threadIdx.x;
    const int wid = t >> 5, lane = t & 31;
    const int nBase = blockIdx.y * TILE_N;
    const int mBase = blockIdx.x * TILE_M;
    const int nOff = (wid >> 2) * 64;     // 2 warp-rows
    const int mOff = (wid & 3) * 32;      // 4 warp-cols

    const char* Xp = (const char*)g_xh + (size_t)nBase * 512;   // 512 B/row
    const char* Yp = (const char*)g_yh + (size_t)mBase * 512;

    // acc[mi][n8 block][2 regs], each reg = f16x2 (2 m-cols)
    uint32_t acc[4][4][2];
    #pragma unroll
    for (int mi = 0; mi < 4; mi++)
        #pragma unroll
        for (int j = 0; j < 4; j++) { acc[mi][j][0] = 0u; acc[mi][j][1] = 0u; }

    // Loader for chunk c into stage s: A 1024x16B, B 1024x16B over 256 threads
    #define LOAD_CHUNK(c, s) do {                                              \
        int bkb = (c) * BKB;                                                   \
        _Pragma("unroll")                                                      \
        for (int i = 0; i < 4; i++) {                                          \
            int idx = t + 256 * i; int r = idx >> 3; int kb = (idx & 7) * 16;  \
            cp16(sb + SM_A(s) + SWZ(r * 128 + kb),                             \
                 Xp + (size_t)r * 512 + bkb + kb);                             \
        }                                                                      \
        _Pragma("unroll")                                                      \
        for (int i = 0; i < 4; i++) {                                          \
            int idx = t + 256 * i; int r = idx >> 3; int kb = (idx & 7) * 16;  \
            cp16(sb + SM_B(s) + SWZ(r * 128 + kb),                             \
                 Yp + (size_t)r * 512 + bkb + kb);                             \
        }                                                                      \
        CP_COMMIT();                                                           \
    } while (0)

    LOAD_CHUNK(0, 0);
    LOAD_CHUNK(1, 1);

    // ldmatrix lane addressing (HW-verified layout from R4/R5/R7)
    const int lrow = (lane & 7) + ((lane >> 3) & 1) * 8;
    const int lkb  = (lane >> 4) * 16;

    for (int c = 0; c < NCHUNK; c++) {
        if (c < NCHUNK - 1) CP_WAIT(1); else CP_WAIT(0);
        __syncthreads();
        const int s = c & 1;

        #pragma unroll
        for (int kk = 0; kk < 4; kk++) {          // 4 x k16 per 128B chunk
            uint32_t af[4][4], bf[2][4];
            #pragma unroll
            for (int mi = 0; mi < 4; mi++) {
                uint32_t addr = sb + SM_A(s)
                    + SWZ((nOff + mi * 16 + lrow) * 128 + kk * 32 + lkb);
                LDSM4(af[mi], addr);
            }
            #pragma unroll
            for (int nj = 0; nj < 2; nj++) {
                uint32_t addr = sb + SM_B(s)
                    + SWZ((mOff + nj * 16 + lrow) * 128 + kk * 32 + lkb);
                LDSM4(bf[nj], addr);
            }
            #pragma unroll
            for (int mi = 0; mi < 4; mi++)
                #pragma unroll
                for (int nj = 0; nj < 2; nj++) {
                    MMAF16(acc[mi][2*nj],     af[mi], bf[nj][0], bf[nj][2]);
                    MMAF16(acc[mi][2*nj + 1], af[mi], bf[nj][1], bf[nj][3]);
                }
        }
        __syncthreads();
        if (c + 2 < NCHUNK) LOAD_CHUNK(c + 2, s);
    }

    // Emit candidates. reg r: rows lane>>2 (+8 for r=1); cols 2(lane&3)+{0,1}
    const int rBase = nBase + nOff + (lane >> 2);
    const int cBase = mBase + mOff + 2 * (lane & 3);
    #pragma unroll
    for (int mi = 0; mi < 4; mi++)
        #pragma unroll
        for (int j = 0; j < 4; j++)
            #pragma unroll
            for (int r = 0; r < 2; r++) {
                __half2 h = *reinterpret_cast<__half2*>(&acc[mi][j][r]);
                float c0 = __low2float(h), c1 = __high2float(h);
                if (c0 > SCREEN_T) {
                    int idx = atomicAdd(&g_cnt, 1);
                    if (idx < CAP)
                        g_pairs[idx] = make_int2(rBase + mi*16 + r*8, cBase + j*8);
                }
                if (c1 > SCREEN_T) {
                    int idx = atomicAdd(&g_cnt, 1);
                    if (idx < CAP)
                        g_pairs[idx] = make_int2(rBase + mi*16 + r*8, cBase + j*8 + 1);
                }
            }
    #undef LOAD_CHUNK
}

// ---------------------------------------------------------------------------
// Exact fp32 recompute of candidates: dot + expf + atomicAdd. 1 warp/pair.
// ---------------------------------------------------------------------------
__global__ void __launch_bounds__(256) recompute_kernel(float* __restrict__ out)
{
    int lane = threadIdx.x & 31;
    int w    = (blockIdx.x * blockDim.x + threadIdx.x) >> 5;
    int nw   = (gridDim.x * blockDim.x) >> 5;
    int cnt  = *(volatile int*)&g_cnt;
    if (cnt > CAP) cnt = CAP;

    for (int i = w; i < cnt; i += nw) {
        int2 p = g_pairs[i];
        const float4* x = reinterpret_cast<const float4*>(g_xn + (size_t)p.x * D);
        const float4* y = reinterpret_cast<const float4*>(g_yn + (size_t)p.y * D);
        float4 xa = x[lane], xb = x[lane + 32];
        float4 ya = y[lane], yb = y[lane + 32];
        float s = xa.x*ya.x + xa.y*ya.y + xa.z*ya.z + xa.w*ya.w
                + xb.x*yb.x + xb.y*yb.y + xb.z*yb.z + xb.w*yb.w;
        #pragma unroll
        for (int off = 16; off > 0; off >>= 1)
            s += __shfl_xor_sync(0xFFFFFFFFu, s, off);
        if (lane == 0) {
            float dd = s - 1.0f;
            float e = expf(LOG_NORM - HALF_INV_SIG2 * dd * dd);
            if (e != 0.0f) atomicAdd(&out[p.y], e);
        }
    }
}

// ---------------------------------------------------------------------------
extern "C" void kernel_launch(void* const* d_in, const int* in_sizes, int n_in,
                              void* d_out, int out_size)
{
    const float* Ex = (const float*)d_in[0];
    const float* Ey = (const float*)d_in[1];
    float* out = (float*)d_out;

    int N = in_sizes[0] / D;   // 8192
    int M = in_sizes[1] / D;   // 8192

    cudaFuncSetAttribute(screen_kernel,
                         cudaFuncAttributeMaxDynamicSharedMemorySize, SMEM_TOTAL);

    normsplit_kernel<<<(N + M + 7) / 8, 256>>>(Ex, Ey, N, M, out);

    dim3 grid(M / TILE_M, N / TILE_N);
    screen_kernel<<<grid, NT, SMEM_TOTAL>>>();

    recompute_kernel<<<64, 256>>>(out);
}